// round 3
// baseline (speedup 1.0000x reference)
#include <cuda_runtime.h>

typedef unsigned long long u64;

// x [16,3,256,256] f32, thetas[12], phis[3] -> out [16,1,128,128] f32
#define P_TOTAL (16 * 128 * 128)   // 262144 patches, 1 thread each

__device__ float g_cu[12][4];
__device__ float g_ph[3][2];

__global__ void prep_kernel(const float* __restrict__ thetas,
                            const float* __restrict__ phis) {
    int t = threadIdx.x;
    if (t < 12) {
        float s, c;
        sincosf(0.5f * thetas[t], &s, &c);
        g_cu[t][0] = s;   g_cu[t][1] = -c;   // f1 = sin - i cos
        g_cu[t][2] = -s;  g_cu[t][3] = -c;   // f2 = -sin - i cos
    }
    if (t < 3) {
        float s, c;
        sincosf(phis[t], &s, &c);
        g_ph[t][0] = c;   g_ph[t][1] = s;
    }
}

// ---- packed f32x2 helpers (lanes: lo = w0=0 branch "a", hi = w0=1 branch "b") ----
__device__ __forceinline__ u64 pk2(float lo, float hi) {
    u64 r; asm("mov.b64 %0,{%1,%2};" : "=l"(r) : "f"(lo), "f"(hi)); return r;
}
__device__ __forceinline__ u64 pk2b(float v) { return pk2(v, v); }
__device__ __forceinline__ void upk2(float& lo, float& hi, u64 v) {
    asm("mov.b64 {%0,%1},%2;" : "=f"(lo), "=f"(hi) : "l"(v));
}
__device__ __forceinline__ u64 fma2(u64 a, u64 b, u64 c) {
    u64 d; asm("fma.rn.f32x2 %0,%1,%2,%3;" : "=l"(d) : "l"(a), "l"(b), "l"(c)); return d;
}
__device__ __forceinline__ u64 mul2(u64 a, u64 b) {
    u64 d; asm("mul.rn.f32x2 %0,%1,%2;" : "=l"(d) : "l"(a), "l"(b)); return d;
}
__device__ __forceinline__ u64 neg2(u64 a) {
    const u64 SGN = 0x8000000080000000ULL;
    u64 d; asm("xor.b64 %0,%1,%2;" : "=l"(d) : "l"(a), "l"(SGN)); return d;
}

// 16-amp space over wires 1-4: n = w1*8 + w2*4 + w3*2 + w4
__global__ void __launch_bounds__(256, 2)
sim_kernel(const float* __restrict__ x, float* __restrict__ out) {
    int p   = blockIdx.x * 256 + threadIdx.x;
    int b   = p >> 14;
    int rem = p & 16383;
    int i   = rem >> 7;
    int j   = rem & 127;

    const float2* __restrict__ x2 = (const float2*)x;

    u64 sr[16], si[16];

    // CU (ctrl,tgt) masks: (w1->w2),(w2->w3),(w3->w4),(w4->w1)
    const int cm[4] = {8, 4, 2, 1};
    const int tm[4] = {4, 2, 1, 8};

    // ================= Layer 0: product state (both lanes identical) =========
    {
        int base = ((b * 3 + 0) * 256 + 2 * i) * 128 + j;
        float2 v0 = x2[base];
        float2 v1 = x2[base + 128];
        float ang[4] = {v0.x, v0.y, v1.x, v1.y};
        float cw[4], sw[4];
#pragma unroll
        for (int w = 0; w < 4; w++) __sincosf(0.5f * ang[w], &sw[w], &cw[w]);

        // amp(n) = m(n) * (-i)^popc(n), m real, include 1/sqrt2
        float c0 = cw[0] * 0.70710678118654752f;
        float s0 = sw[0] * 0.70710678118654752f;
        float abv[4] = { c0 * cw[1], c0 * sw[1], s0 * cw[1], s0 * sw[1] };
        float cdv[4] = { cw[2] * cw[3], cw[2] * sw[3], sw[2] * cw[3], sw[2] * sw[3] };
#pragma unroll
        for (int n = 0; n < 16; n++) {
            float m = abv[n >> 2] * cdv[n & 3];
            int pc = __popc(n) & 3;
            if (pc == 0)      { sr[n] = pk2b(m);  si[n] = 0ULL;      }
            else if (pc == 1) { sr[n] = 0ULL;     si[n] = pk2b(-m);  }
            else if (pc == 2) { sr[n] = pk2b(-m); si[n] = 0ULL;      }
            else              { sr[n] = 0ULL;     si[n] = pk2b(m);   }
        }
    }

    // ---- Layer-0 CU gates ----
#pragma unroll
    for (int w = 0; w < 4; w++) {
        u64 f1r = pk2b(g_cu[w][0]), f1i = pk2b(g_cu[w][1]);
        u64 f2r = pk2b(g_cu[w][2]), f2i = pk2b(g_cu[w][3]);
        u64 nf1i = neg2(f1i), nf2i = neg2(f2i);
#pragma unroll
        for (int k = 0; k < 16; k++) {
            if ((k & cm[w]) && !(k & tm[w])) {
                int k1 = k | tm[w];
                u64 a0r = sr[k],  a0i = si[k];
                u64 a1r = sr[k1], a1i = si[k1];
                sr[k]  = fma2(nf1i, a1i, mul2(f1r, a1r));
                si[k]  = fma2(f1i,  a1r, mul2(f1r, a1i));
                sr[k1] = fma2(nf2i, a0i, mul2(f2r, a0r));
                si[k1] = fma2(f2i,  a0r, mul2(f2r, a0i));
            }
        }
    }

    // ---- CPhase layer 0: phase e^{i phi} on (w0=1 & w1=1) -> hi lane, n&8 ----
    {
        u64 pr = pk2(1.0f, g_ph[0][0]);
        u64 pi = pk2(0.0f, g_ph[0][1]);
        u64 npi = neg2(pi);
#pragma unroll
        for (int n = 8; n < 16; n++) {
            u64 ar = sr[n], ai = si[n];
            sr[n] = fma2(npi, ai, mul2(pr, ar));
            si[n] = fma2(pi,  ar, mul2(pr, ai));
        }
    }

    float Cacc = 1.0f;   // accumulated uniform RX cos scale (layers 1,2)

    // ================= Layers 1, 2 =================
#pragma unroll
    for (int L = 1; L < 3; L++) {
        int base = ((b * 3 + L) * 256 + 2 * i) * 128 + j;
        float2 v0 = x2[base];
        float2 v1 = x2[base + 128];
        float ang[4] = {v0.x, v0.y, v1.x, v1.y};

        // RX via tan trick: RX/c = [[1,-it],[-it,1]], fold c into Cacc
#pragma unroll
        for (int w = 0; w < 4; w++) {
            float s, c;
            __sincosf(0.5f * ang[w], &s, &c);
            Cacc *= c;
            u64 t = pk2b(__fdividef(s, c));
            u64 nt = neg2(t);
            int m = 8 >> w;
#pragma unroll
            for (int k = 0; k < 16; k++) {
                if (!(k & m)) {
                    int k1 = k | m;
                    u64 a0r = sr[k],  a0i = si[k];
                    u64 a1r = sr[k1], a1i = si[k1];
                    sr[k]  = fma2(t,  a1i, a0r);
                    si[k]  = fma2(nt, a1r, a0i);
                    sr[k1] = fma2(t,  a0i, a1r);
                    si[k1] = fma2(nt, a0r, a1i);
                }
            }
        }
        // CU gates
#pragma unroll
        for (int w = 0; w < 4; w++) {
            int gi = 4 * L + w;
            u64 f1r = pk2b(g_cu[gi][0]), f1i = pk2b(g_cu[gi][1]);
            u64 f2r = pk2b(g_cu[gi][2]), f2i = pk2b(g_cu[gi][3]);
            u64 nf1i = neg2(f1i), nf2i = neg2(f2i);
#pragma unroll
            for (int k = 0; k < 16; k++) {
                if ((k & cm[w]) && !(k & tm[w])) {
                    int k1 = k | tm[w];
                    u64 a0r = sr[k],  a0i = si[k];
                    u64 a1r = sr[k1], a1i = si[k1];
                    sr[k]  = fma2(nf1i, a1i, mul2(f1r, a1r));
                    si[k]  = fma2(f1i,  a1r, mul2(f1r, a1i));
                    sr[k1] = fma2(nf2i, a0i, mul2(f2r, a0r));
                    si[k1] = fma2(f2i,  a0r, mul2(f2r, a0i));
                }
            }
        }
        // CPhase (hi lane, n&8)
        {
            u64 pr = pk2(1.0f, g_ph[L][0]);
            u64 pi = pk2(0.0f, g_ph[L][1]);
            u64 npi = neg2(pi);
#pragma unroll
            for (int n = 8; n < 16; n++) {
                u64 ar = sr[n], ai = si[n];
                sr[n] = fma2(npi, ai, mul2(pr, ar));
                si[n] = fma2(pi,  ar, mul2(pr, ai));
            }
        }
    }

    // Final H on wire0 + <Z0> = 2 * C^2 * sum Re(a conj(b)) (cross-lane)
    float acc = 0.f;
#pragma unroll
    for (int k = 0; k < 16; k++) {
        float arl, brl, ail, bil;
        upk2(arl, brl, sr[k]);
        upk2(ail, bil, si[k]);
        acc = fmaf(arl, brl, acc);
        acc = fmaf(ail, bil, acc);
    }
    out[p] = 2.0f * Cacc * Cacc * acc;
}

extern "C" void kernel_launch(void* const* d_in, const int* in_sizes, int n_in,
                              void* d_out, int out_size) {
    const float* x      = (const float*)d_in[0];
    const float* thetas = (const float*)d_in[1];
    const float* phis   = (const float*)d_in[2];
    float* out = (float*)d_out;

    prep_kernel<<<1, 32>>>(thetas, phis);
    sim_kernel<<<P_TOTAL / 256, 256>>>(x, out);
}

// round 4
// speedup vs baseline: 1.3588x; 1.3588x over previous
#include <cuda_runtime.h>

typedef unsigned long long u64;

// x [16,3,256,256] f32, thetas[12], phis[3] -> out [16,1,128,128] f32
// 131072 patch-pairs; 2 threads per pair (w0=0 / w0=1 branch); 2 patches in f32x2 lanes.
#define NTHREADS (16 * 128 * 64 * 2)   // 262144

__device__ float g_cu[12][4];
__device__ float g_ph[3][2];

__global__ void prep_kernel(const float* __restrict__ thetas,
                            const float* __restrict__ phis) {
    int t = threadIdx.x;
    if (t < 12) {
        float s, c;
        sincosf(0.5f * thetas[t], &s, &c);
        g_cu[t][0] = s;   g_cu[t][1] = -c;   // f1 = sin - i cos
        g_cu[t][2] = -s;  g_cu[t][3] = -c;   // f2 = -sin - i cos
    }
    if (t < 3) {
        float s, c;
        sincosf(phis[t], &s, &c);
        g_ph[t][0] = c;   g_ph[t][1] = s;
    }
}

// ---- packed f32x2 helpers (lanes = 2 adjacent patches) ----
__device__ __forceinline__ u64 pk2(float lo, float hi) {
    u64 r; asm("mov.b64 %0,{%1,%2};" : "=l"(r) : "f"(lo), "f"(hi)); return r;
}
__device__ __forceinline__ u64 pk2b(float v) { return pk2(v, v); }
__device__ __forceinline__ void upk2(float& lo, float& hi, u64 v) {
    asm("mov.b64 {%0,%1},%2;" : "=f"(lo), "=f"(hi) : "l"(v));
}
__device__ __forceinline__ u64 fma2(u64 a, u64 b, u64 c) {
    u64 d; asm("fma.rn.f32x2 %0,%1,%2,%3;" : "=l"(d) : "l"(a), "l"(b), "l"(c)); return d;
}
__device__ __forceinline__ u64 mul2(u64 a, u64 b) {
    u64 d; asm("mul.rn.f32x2 %0,%1,%2;" : "=l"(d) : "l"(a), "l"(b)); return d;
}
__device__ __forceinline__ u64 neg2(u64 a) {
    const u64 SGN = 0x8000000080000000ULL;
    u64 d; asm("xor.b64 %0,%1,%2;" : "=l"(d) : "l"(a), "l"(SGN)); return d;
}

struct CS { u64 c, s; };
__device__ __forceinline__ CS cs2(float alo, float ahi) {
    float sl, cl, sh, ch;
    __sincosf(0.5f * alo, &sl, &cl);
    __sincosf(0.5f * ahi, &sh, &ch);
    CS r; r.c = pk2(cl, ch); r.s = pk2(sl, sh); return r;
}
struct CT { u64 c, t; };  // cos (for scale) + tan (for butterflies)
__device__ __forceinline__ CT ct2(float alo, float ahi) {
    float sl, cl, sh, ch;
    __sincosf(0.5f * alo, &sl, &cl);
    __sincosf(0.5f * ahi, &sh, &ch);
    CT r; r.c = pk2(cl, ch);
    r.t = pk2(__fdividef(sl, cl), __fdividef(sh, ch));
    return r;
}

// 16-amp space over wires 1-4: n = w1*8 + w2*4 + w3*2 + w4
__global__ void __launch_bounds__(256, 2)
sim_kernel(const float* __restrict__ x, float* __restrict__ out) {
    int T      = blockIdx.x * 256 + threadIdx.x;
    int q      = T >> 1;          // patch-pair index
    int branch = T & 1;           // 0: w0=0 branch, 1: w0=1 branch
    int b   = q >> 13;
    int rem = q & 8191;
    int i   = rem >> 6;
    int jp  = rem & 63;

    const float4* __restrict__ x4 = (const float4*)x;

    u64 sr[16], si[16];

    const int cm[4] = {8, 4, 2, 1};
    const int tm[4] = {4, 2, 1, 8};

    // ================= Layer 0: product state (branches identical) ===========
    {
        int base = ((b * 3 + 0) * 256 + 2 * i) * 64 + jp;
        float4 v0 = x4[base];
        float4 v1 = x4[base + 64];
        CS g0 = cs2(v0.x, v0.z), g1 = cs2(v0.y, v0.w);
        CS g2 = cs2(v1.x, v1.z), g3 = cs2(v1.y, v1.w);

        u64 INV2 = pk2b(0.70710678118654752f);
        u64 c0 = mul2(g0.c, INV2), s0 = mul2(g0.s, INV2);
        u64 ab[4] = { mul2(c0, g1.c), mul2(c0, g1.s), mul2(s0, g1.c), mul2(s0, g1.s) };
        u64 cd[4] = { mul2(g2.c, g3.c), mul2(g2.c, g3.s), mul2(g2.s, g3.c), mul2(g2.s, g3.s) };
#pragma unroll
        for (int n = 0; n < 16; n++) {
            u64 m = mul2(ab[n >> 2], cd[n & 3]);
            int pc = __popc(n) & 3;
            if (pc == 0)      { sr[n] = m;        si[n] = 0ULL;     }
            else if (pc == 1) { sr[n] = 0ULL;     si[n] = neg2(m);  }
            else if (pc == 2) { sr[n] = neg2(m);  si[n] = 0ULL;     }
            else              { sr[n] = 0ULL;     si[n] = m;        }
        }
    }

    // ---- Layer-0 CU gates ----
#pragma unroll
    for (int w = 0; w < 4; w++) {
        u64 f1r = pk2b(g_cu[w][0]), f1i = pk2b(g_cu[w][1]);
        u64 f2r = pk2b(g_cu[w][2]), f2i = pk2b(g_cu[w][3]);
        u64 nf1i = neg2(f1i), nf2i = neg2(f2i);
#pragma unroll
        for (int k = 0; k < 16; k++) {
            if ((k & cm[w]) && !(k & tm[w])) {
                int k1 = k | tm[w];
                u64 a0r = sr[k],  a0i = si[k];
                u64 a1r = sr[k1], a1i = si[k1];
                sr[k]  = fma2(nf1i, a1i, mul2(f1r, a1r));
                si[k]  = fma2(f1i,  a1r, mul2(f1r, a1i));
                sr[k1] = fma2(nf2i, a0i, mul2(f2r, a0r));
                si[k1] = fma2(f2i,  a0r, mul2(f2r, a0i));
            }
        }
    }

    // ---- CPhase layer 0: phase on (w0=1 & w1=1) -> branch-1 thread, n&8 ----
    if (branch) {
        u64 pr = pk2b(g_ph[0][0]), pi = pk2b(g_ph[0][1]);
        u64 npi = neg2(pi);
#pragma unroll
        for (int n = 8; n < 16; n++) {
            u64 ar = sr[n], ai = si[n];
            sr[n] = fma2(npi, ai, mul2(pr, ar));
            si[n] = fma2(pi,  ar, mul2(pr, ai));
        }
    }

    u64 Cacc = pk2b(1.0f);   // packed uniform RX cos scale (per patch lane)

    // ================= Layers 1, 2 =================
#pragma unroll
    for (int L = 1; L < 3; L++) {
        int base = ((b * 3 + L) * 256 + 2 * i) * 64 + jp;
        float4 v0 = x4[base];
        float4 v1 = x4[base + 64];
        CT g[4] = { ct2(v0.x, v0.z), ct2(v0.y, v0.w),
                    ct2(v1.x, v1.z), ct2(v1.y, v1.w) };
        // RX via tan trick: RX/c = [[1,-it],[-it,1]]
#pragma unroll
        for (int w = 0; w < 4; w++) {
            Cacc = mul2(Cacc, g[w].c);
            u64 t = g[w].t, nt = neg2(t);
            int m = 8 >> w;
#pragma unroll
            for (int k = 0; k < 16; k++) {
                if (!(k & m)) {
                    int k1 = k | m;
                    u64 a0r = sr[k],  a0i = si[k];
                    u64 a1r = sr[k1], a1i = si[k1];
                    sr[k]  = fma2(t,  a1i, a0r);
                    si[k]  = fma2(nt, a1r, a0i);
                    sr[k1] = fma2(t,  a0i, a1r);
                    si[k1] = fma2(nt, a0r, a1i);
                }
            }
        }
        // CU gates
#pragma unroll
        for (int w = 0; w < 4; w++) {
            int gi = 4 * L + w;
            u64 f1r = pk2b(g_cu[gi][0]), f1i = pk2b(g_cu[gi][1]);
            u64 f2r = pk2b(g_cu[gi][2]), f2i = pk2b(g_cu[gi][3]);
            u64 nf1i = neg2(f1i), nf2i = neg2(f2i);
#pragma unroll
            for (int k = 0; k < 16; k++) {
                if ((k & cm[w]) && !(k & tm[w])) {
                    int k1 = k | tm[w];
                    u64 a0r = sr[k],  a0i = si[k];
                    u64 a1r = sr[k1], a1i = si[k1];
                    sr[k]  = fma2(nf1i, a1i, mul2(f1r, a1r));
                    si[k]  = fma2(f1i,  a1r, mul2(f1r, a1i));
                    sr[k1] = fma2(nf2i, a0i, mul2(f2r, a0r));
                    si[k1] = fma2(f2i,  a0r, mul2(f2r, a0i));
                }
            }
        }
        // CPhase (branch-1 thread, n&8)
        if (branch) {
            u64 pr = pk2b(g_ph[L][0]), pi = pk2b(g_ph[L][1]);
            u64 npi = neg2(pi);
#pragma unroll
            for (int n = 8; n < 16; n++) {
                u64 ar = sr[n], ai = si[n];
                sr[n] = fma2(npi, ai, mul2(pr, ar));
                si[n] = fma2(pi,  ar, mul2(pr, ai));
            }
        }
    }

    // Final H on wire0 + <Z0> = 2*C^2 * sum_k Re(a_k conj(b_k))
    // Elementwise cross-thread dot via shfl_xor(1); symmetric, both threads get it.
    u64 acc = 0ULL;
#pragma unroll
    for (int k = 0; k < 16; k++) {
        u64 or_ = __shfl_xor_sync(0xFFFFFFFFu, sr[k], 1);
        u64 oi_ = __shfl_xor_sync(0xFFFFFFFFu, si[k], 1);
        acc = fma2(sr[k], or_, acc);
        acc = fma2(si[k], oi_, acc);
    }
    // scale by 2*C^2 (C identical in both threads of the pair)
    u64 C2 = mul2(Cacc, Cacc);
    acc = mul2(acc, mul2(C2, pk2b(2.0f)));

    if (branch == 0) {
        float lo, hi;
        upk2(lo, hi, acc);
        ((float2*)out)[q] = make_float2(lo, hi);
    }
}

extern "C" void kernel_launch(void* const* d_in, const int* in_sizes, int n_in,
                              void* d_out, int out_size) {
    const float* x      = (const float*)d_in[0];
    const float* thetas = (const float*)d_in[1];
    const float* phis   = (const float*)d_in[2];
    float* out = (float*)d_out;

    prep_kernel<<<1, 32>>>(thetas, phis);
    sim_kernel<<<NTHREADS / 256, 256>>>(x, out);
}

// round 5
// speedup vs baseline: 1.6283x; 1.1983x over previous
#include <cuda_runtime.h>

typedef unsigned long long u64;

// x [16,3,256,256] f32, thetas[12], phis[3] -> out [16,1,128,128] f32
#define PPAIRS (16 * 128 * 64)   // 131072 threads, 2 patches each

__device__ float g_cu[12][4];
__device__ float g_ph[3][2];

__global__ void prep_kernel(const float* __restrict__ thetas,
                            const float* __restrict__ phis) {
    int t = threadIdx.x;
    if (t < 12) {
        float s, c;
        sincosf(0.5f * thetas[t], &s, &c);
        g_cu[t][0] = s;   g_cu[t][1] = -c;   // f1 = sin - i cos
        g_cu[t][2] = -s;  g_cu[t][3] = -c;   // f2 = -sin - i cos
    }
    if (t < 3) {
        float s, c;
        sincosf(phis[t], &s, &c);
        g_ph[t][0] = c;   g_ph[t][1] = s;
    }
}

// ---- packed f32x2 helpers (lanes = 2 adjacent patches) ----
__device__ __forceinline__ u64 pk2(float lo, float hi) {
    u64 r; asm("mov.b64 %0,{%1,%2};" : "=l"(r) : "f"(lo), "f"(hi)); return r;
}
__device__ __forceinline__ u64 pk2b(float v) { return pk2(v, v); }
__device__ __forceinline__ void upk2(float& lo, float& hi, u64 v) {
    asm("mov.b64 {%0,%1},%2;" : "=f"(lo), "=f"(hi) : "l"(v));
}
__device__ __forceinline__ u64 fma2(u64 a, u64 b, u64 c) {
    u64 d; asm("fma.rn.f32x2 %0,%1,%2,%3;" : "=l"(d) : "l"(a), "l"(b), "l"(c)); return d;
}
__device__ __forceinline__ u64 mul2(u64 a, u64 b) {
    u64 d; asm("mul.rn.f32x2 %0,%1,%2;" : "=l"(d) : "l"(a), "l"(b)); return d;
}
__device__ __forceinline__ u64 neg2(u64 a) {
    const u64 SGN = 0x8000000080000000ULL;
    u64 d; asm("xor.b64 %0,%1,%2;" : "=l"(d) : "l"(a), "l"(SGN)); return d;
}

struct CS { u64 c, s; };
__device__ __forceinline__ CS cs2(float alo, float ahi) {
    float sl, cl, sh, ch;
    __sincosf(0.5f * alo, &sl, &cl);
    __sincosf(0.5f * ahi, &sh, &ch);
    CS r; r.c = pk2(cl, ch); r.s = pk2(sl, sh); return r;
}
struct CT { u64 c, t; };  // cos (uniform scale) + tan (butterfly)
__device__ __forceinline__ CT ct2(float alo, float ahi) {
    float sl, cl, sh, ch;
    __sincosf(0.5f * alo, &sl, &cl);
    __sincosf(0.5f * ahi, &sh, &ch);
    CT r; r.c = pk2(cl, ch);
    r.t = pk2(__fdividef(sl, cl), __fdividef(sh, ch));
    return r;
}

// Full 32-amp state: k = w0*16 + n, n = w1*8 + w2*4 + w3*2 + w4
__global__ void __launch_bounds__(128)
sim_kernel(const float* __restrict__ x, float* __restrict__ out) {
    int q   = blockIdx.x * 128 + threadIdx.x;
    int b   = q >> 13;
    int rem = q & 8191;
    int i   = rem >> 6;
    int jp  = rem & 63;

    const float4* __restrict__ x4 = (const float4*)x;

    u64 sr[32], si[32];

    // CU (ctrl,tgt) masks within 4-wire space
    const int cm[4] = {8, 4, 2, 1};
    const int tm[4] = {4, 2, 1, 8};

    // ================= Layer 0: product state (16 amps) =================
    {
        int base = ((b * 3 + 0) * 256 + 2 * i) * 64 + jp;
        float4 v0 = x4[base];
        float4 v1 = x4[base + 64];
        CS g0 = cs2(v0.x, v0.z), g1 = cs2(v0.y, v0.w);
        CS g2 = cs2(v1.x, v1.z), g3 = cs2(v1.y, v1.w);

        u64 INV2 = pk2b(0.70710678118654752f);
        u64 c0 = mul2(g0.c, INV2), s0 = mul2(g0.s, INV2);
        u64 ab[4] = { mul2(c0, g1.c), mul2(c0, g1.s), mul2(s0, g1.c), mul2(s0, g1.s) };
        u64 cd[4] = { mul2(g2.c, g3.c), mul2(g2.c, g3.s), mul2(g2.s, g3.c), mul2(g2.s, g3.s) };
#pragma unroll
        for (int n = 0; n < 16; n++) {
            u64 m = mul2(ab[n >> 2], cd[n & 3]);
            int pc = __popc(n) & 3;
            if (pc == 0)      { sr[n] = m;        si[n] = 0ULL;     }
            else if (pc == 1) { sr[n] = 0ULL;     si[n] = neg2(m);  }
            else if (pc == 2) { sr[n] = neg2(m);  si[n] = 0ULL;     }
            else              { sr[n] = 0ULL;     si[n] = m;        }
        }
    }

    // ---- Layer-0 CU gates on the 16-amp state (wire0 untouched yet) ----
#pragma unroll
    for (int w = 0; w < 4; w++) {
        u64 f1r = pk2b(g_cu[w][0]), f1i = pk2b(g_cu[w][1]);
        u64 f2r = pk2b(g_cu[w][2]), f2i = pk2b(g_cu[w][3]);
        u64 nf1i = neg2(f1i), nf2i = neg2(f2i);
#pragma unroll
        for (int k = 0; k < 16; k++) {
            if ((k & cm[w]) && !(k & tm[w])) {
                int k1 = k | tm[w];
                u64 a0r = sr[k],  a0i = si[k];
                u64 a1r = sr[k1], a1i = si[k1];
                sr[k]  = fma2(nf1i, a1i, mul2(f1r, a1r));
                si[k]  = fma2(f1i,  a1r, mul2(f1r, a1i));
                sr[k1] = fma2(nf2i, a0i, mul2(f2r, a0r));
                si[k1] = fma2(f2i,  a0r, mul2(f2r, a0i));
            }
        }
    }

    // ---- Split into wire0 branches at CPhase-0: upper = lower, phased on w1=1
    {
        u64 pr = pk2b(g_ph[0][0]), pi = pk2b(g_ph[0][1]);
        u64 npi = neg2(pi);
#pragma unroll
        for (int n = 0; n < 16; n++) {
            if (n & 8) {
                sr[16 + n] = fma2(npi, si[n], mul2(pr, sr[n]));
                si[16 + n] = fma2(pi,  sr[n], mul2(pr, si[n]));
            } else {
                sr[16 + n] = sr[n];
                si[16 + n] = si[n];
            }
        }
    }

    u64 Cacc = pk2b(1.0f);  // packed uniform RX cos scale (layers 1,2)

    // ================= Layers 1, 2 =================
#pragma unroll
    for (int L = 1; L < 3; L++) {
        int base = ((b * 3 + L) * 256 + 2 * i) * 64 + jp;
        float4 v0 = x4[base];
        float4 v1 = x4[base + 64];
        CT g[4] = { ct2(v0.x, v0.z), ct2(v0.y, v0.w),
                    ct2(v1.x, v1.z), ct2(v1.y, v1.w) };

        // RX via tan trick: RX/c = [[1,-it],[-it,1]]  (dense, 32 amps)
#pragma unroll
        for (int w = 0; w < 4; w++) {
            Cacc = mul2(Cacc, g[w].c);
            u64 t = g[w].t, nt = neg2(t);
            int m = 8 >> w;
#pragma unroll
            for (int k = 0; k < 32; k++) {
                if (!(k & m)) {
                    int k1 = k | m;
                    u64 a0r = sr[k],  a0i = si[k];
                    u64 a1r = sr[k1], a1i = si[k1];
                    sr[k]  = fma2(t,  a1i, a0r);
                    si[k]  = fma2(nt, a1r, a0i);
                    sr[k1] = fma2(t,  a0i, a1r);
                    si[k1] = fma2(nt, a0r, a1i);
                }
            }
        }
        // CU gates (32 amps)
#pragma unroll
        for (int w = 0; w < 4; w++) {
            int gi = 4 * L + w;
            u64 f1r = pk2b(g_cu[gi][0]), f1i = pk2b(g_cu[gi][1]);
            u64 f2r = pk2b(g_cu[gi][2]), f2i = pk2b(g_cu[gi][3]);
            u64 nf1i = neg2(f1i), nf2i = neg2(f2i);
#pragma unroll
            for (int k = 0; k < 32; k++) {
                if ((k & cm[w]) && !(k & tm[w])) {
                    int k1 = k | tm[w];
                    u64 a0r = sr[k],  a0i = si[k];
                    u64 a1r = sr[k1], a1i = si[k1];
                    sr[k]  = fma2(nf1i, a1i, mul2(f1r, a1r));
                    si[k]  = fma2(f1i,  a1r, mul2(f1r, a1i));
                    sr[k1] = fma2(nf2i, a0i, mul2(f2r, a0r));
                    si[k1] = fma2(f2i,  a0r, mul2(f2r, a0i));
                }
            }
        }
        // CPhase: apply in-state only for layer 1; layer 2 folds into reduce
        if (L == 1) {
            u64 pr = pk2b(g_ph[1][0]), pi = pk2b(g_ph[1][1]);
            u64 npi = neg2(pi);
#pragma unroll
            for (int k = 0; k < 32; k++) {
                if ((k & 24) == 24) {
                    u64 ar = sr[k], ai = si[k];
                    sr[k] = fma2(npi, ai, mul2(pr, ar));
                    si[k] = fma2(pi,  ar, mul2(pr, ai));
                }
            }
        }
    }

    // Final: ev = 2*C^2 * Re[ S0 + e^{i phi2} S1 ],
    //  S0 = sum_{n&8==0} conj(a_n) b_n,  S1 = sum_{n&8} conj(a_n) b_n
    //  Re(conj(a)b) = ar*br + ai*bi ;  Im(conj(a)b) = ar*bi - ai*br
    u64 accR0 = 0ULL, accR1 = 0ULL, accI1 = 0ULL;
#pragma unroll
    for (int n = 0; n < 16; n++) {
        u64 ar = sr[n], ai = si[n];
        u64 br = sr[n + 16], bi = si[n + 16];
        if (n & 8) {
            accR1 = fma2(ar, br, accR1);
            accR1 = fma2(ai, bi, accR1);
            accI1 = fma2(ar, bi, accI1);
            accI1 = fma2(neg2(ai), br, accI1);
        } else {
            accR0 = fma2(ar, br, accR0);
            accR0 = fma2(ai, bi, accR0);
        }
    }
    u64 cph = pk2b(g_ph[2][0]), sph = pk2b(g_ph[2][1]);
    u64 re = fma2(cph, accR1, accR0);
    re = fma2(neg2(sph), accI1, re);
    u64 C2 = mul2(Cacc, Cacc);
    re = mul2(re, mul2(C2, pk2b(2.0f)));

    float lo, hi;
    upk2(lo, hi, re);
    ((float2*)out)[q] = make_float2(lo, hi);
}

extern "C" void kernel_launch(void* const* d_in, const int* in_sizes, int n_in,
                              void* d_out, int out_size) {
    const float* x      = (const float*)d_in[0];
    const float* thetas = (const float*)d_in[1];
    const float* phis   = (const float*)d_in[2];
    float* out = (float*)d_out;

    prep_kernel<<<1, 32>>>(thetas, phis);
    sim_kernel<<<PPAIRS / 128, 128>>>(x, out);
}